// round 15
// baseline (speedup 1.0000x reference)
#include <cuda_runtime.h>
#include <cuda_fp16.h>
#include <cstdint>

// ---------------------------------------------------------------------------
#define BT      16384
#define DDIM    512
#define NE      8192
#define BETA    0.25

#define ZQ_ELEMS   (BT * DDIM)
#define LOSS_OFF   ZQ_ELEMS
#define IDX_OFF    (ZQ_ELEMS + 1)
#define VAR_OFF    (ZQ_ELEMS + 1 + BT)

#define M_TILE   128
#define N_TILE   256
#define N_TILES  (NE / N_TILE)            // 32
#define KC       128                      // int8 k per stage (128B rows)
#define KSTEPS   (DDIM / KC)              // 4
#define TOT_STAGES (N_TILES * KSTEPS)     // 128

#define A_BYTES  (M_TILE * 128)           // 16384
#define B_BYTES  (N_TILE * 128)           // 32768
#define STAGE_B  (A_BYTES + B_BYTES)      // 49152
#define NSTG     4
#define CAND_OFF (NSTG * STAGE_B)         // 196608
#define CAND_B   (512 * 4 * 16)           // 32768
#define SMEM_DYN (CAND_OFF + CAND_B)      // 229376

#define SZ 20.0f                           // z quant scale
#define SE 1.0e6f                          // emb quant scale
#define MARGIN_S32 20000.0f                // refine threshold in score units
#define FINF __int_as_float(0x7f800000)

// ---------------------------------------------------------------------------
// Device scratch
// ---------------------------------------------------------------------------
__device__ __align__(256) int8_t g_z8[BT * DDIM];   // int8(z*SZ)
__device__ __align__(256) int8_t g_e8[NE * DDIM];   // int8(emb*SE)
__device__ float  g_zf2[BT];
__device__ float  g_en2[NE];
__device__ int    g_idx[BT];
__device__ double g_partial[1024];
__device__ float  g_cd[BT * 32];   // per-row screen scores (-dot_s32), top-2 x16
__device__ int    g_ci[BT * 32];

struct Cand { float d0; int i0; float d1; int i1; };

// ---------------------------------------------------------------------------
__device__ __forceinline__ uint32_t smem_u32(const void* p) {
    uint32_t a;
    asm("{ .reg .u64 t; cvta.to.shared.u64 t, %1; cvt.u32.u64 %0, t; }"
        : "=r"(a) : "l"(p));
    return a;
}
__device__ __forceinline__ void cp16(uint32_t dst, const void* src) {
    asm volatile("cp.async.cg.shared.global [%0], [%1], 16;"
                 :: "r"(dst), "l"(src) : "memory");
}
__device__ __forceinline__ void ldm_x4(uint32_t* r, uint32_t addr) {
    asm volatile("ldmatrix.sync.aligned.m8n8.x4.shared.b16 {%0,%1,%2,%3}, [%4];"
                 : "=r"(r[0]), "=r"(r[1]), "=r"(r[2]), "=r"(r[3]) : "r"(addr));
}
// int8 mma k32, s32 accumulators
__device__ __forceinline__ void imma8(int* c, const uint32_t* a,
                                      const uint32_t* b) {
    asm volatile(
        "mma.sync.aligned.m16n8k32.row.col.s32.s8.s8.s32 "
        "{%0,%1,%2,%3}, {%4,%5,%6,%7}, {%8,%9}, {%0,%1,%2,%3};"
        : "+r"(c[0]), "+r"(c[1]), "+r"(c[2]), "+r"(c[3])
        : "r"(a[0]), "r"(a[1]), "r"(a[2]), "r"(a[3]), "r"(b[0]), "r"(b[1]));
}
__device__ __forceinline__ int8_t q8(float v, float s) {
    float x = rintf(v * s);
    x = fminf(fmaxf(x, -127.0f), 127.0f);
    return (int8_t)(int)x;
}

// ---------------------------------------------------------------------------
// FUSED prep + norms: one pass. Stages 128x64 fp32 chunk in smem, emits int8
// plane (coalesced char4 stores) and accumulates row norm in EXACT serial k
// order (bit-identical to R1 norms — refine depends on it). Device-symbol
// writes from device code only (R5/R6 lesson).
// ---------------------------------------------------------------------------
__global__ void prep_norms_kernel(const float* __restrict__ emb,
                                  const float* __restrict__ z) {
    __shared__ float buf[128][65];
    const bool is_z = blockIdx.x >= (NE / 128);
    const float* x = is_z ? z : emb;
    int8_t* g8 = is_z ? g_z8 : g_e8;
    const float sc = is_z ? SZ : SE;
    const int r0 = (is_z ? (blockIdx.x - NE / 128) : blockIdx.x) * 128;
    float s = 0.0f;
    for (int kc = 0; kc < DDIM; kc += 64) {
        __syncthreads();
#pragma unroll
        for (int i = 0; i < 16; ++i) {
            const int seg = threadIdx.x + i * 128;
            const int r = seg >> 4, c4 = seg & 15;
            float4 v = *reinterpret_cast<const float4*>(
                x + (size_t)(r0 + r) * DDIM + kc + c4 * 4);
            buf[r][c4 * 4 + 0] = v.x; buf[r][c4 * 4 + 1] = v.y;
            buf[r][c4 * 4 + 2] = v.z; buf[r][c4 * 4 + 3] = v.w;
            char4 q;
            q.x = q8(v.x, sc); q.y = q8(v.y, sc);
            q.z = q8(v.z, sc); q.w = q8(v.w, sc);
            *reinterpret_cast<char4*>(
                g8 + (size_t)(r0 + r) * DDIM + kc + c4 * 4) = q;
        }
        __syncthreads();
#pragma unroll
        for (int k = 0; k < 64; ++k) {
            float q = __fmul_rn(buf[threadIdx.x][k], buf[threadIdx.x][k]);
            s = __fadd_rn(s, q);
        }
    }
    if (is_z) g_zf2[r0 + threadIdx.x] = s;
    else      g_en2[r0 + threadIdx.x] = s;
}

// ---------------------------------------------------------------------------
// Pass 1: int8 k32 screen GEMM. Same smem layout / swizzle / ldmatrix as the
// fp16 kernel (int8 k32 fragments are byte-identical to fp16 k16 fragments
// with fp16 slot -> 2 int8). 128B rows now carry k=128 -> half the stages.
// 4-buffer ring, prefetch 2, single barrier, smem top-2 candidates.
// ---------------------------------------------------------------------------
__global__ __launch_bounds__(512, 1) void vq_mma_kernel() {
    extern __shared__ __align__(1024) char dsm[];

    const int tid = threadIdx.x;
    const int l   = tid & 31;
    const int wid = tid >> 5;
    const int wm  = wid & 3;
    const int wn  = wid >> 2;
    const int rowBlock = blockIdx.x * M_TILE;
    const uint32_t sb = smem_u32(dsm);
    Cand* cands = reinterpret_cast<Cand*>(dsm + CAND_OFF) + tid * 4;

    const int arow = l & 15;
    const int agr  = l >> 4;
    const int brow = (l & 7) | ((l >> 4) << 3);
    const int bgr  = (l >> 3) & 1;
    const uint32_t aoffL = (uint32_t)(wm * 32 + arow) * 128;
    const uint32_t boffL = (uint32_t)(wn * 64 + brow) * 128;
    const int aswz = arow & 7;
    const int bswz = l & 7;

    // hoisted loader geometry (6 segs/thread/stage); offsets in BYTES (int8)
    uint32_t dof[6];
    int      soff[6];
#pragma unroll
    for (int i = 0; i < 6; ++i) {
        const int seg = tid + i * 512;
        if (seg < 1024) {
            const int r = seg >> 3, gs = seg & 7;
            dof[i]  = r * 128 + ((gs ^ (r & 7)) << 4);
            soff[i] = (rowBlock + r) * DDIM + gs * 16;   // into g_z8
        } else {
            const int s2 = seg - 1024;
            const int r = s2 >> 3, gs = s2 & 7;
            dof[i]  = A_BYTES + r * 128 + ((gs ^ (r & 7)) << 4);
            soff[i] = r * DDIM + gs * 16;                // into g_e8 (+ tile off)
        }
    }

    float w2[4];
#pragma unroll
    for (int rs = 0; rs < 4; rs++) {
        w2[rs] = FINF;
        cands[rs].d0 = FINF; cands[rs].i0 = 0x7fffffff;
        cands[rs].d1 = FINF; cands[rs].i1 = 0x7fffffff;
    }

    int acc[2][8][4];               // s32 accumulators

    auto load_stage = [&](int s) {
        if (s < TOT_STAGES) {
            const int kcg  = (s % KSTEPS) * KC;
            const int boff = (s / KSTEPS) * (N_TILE * DDIM) + kcg;
#pragma unroll
            for (int i = 0; i < 2; ++i)
                cp16(sb + (s % NSTG) * STAGE_B + dof[i], g_z8 + soff[i] + kcg);
#pragma unroll
            for (int i = 2; i < 6; ++i)
                cp16(sb + (s % NSTG) * STAGE_B + dof[i], g_e8 + soff[i] + boff);
        }
        asm volatile("cp.async.commit_group;" ::: "memory");
    };

    load_stage(0);
    load_stage(1);

    for (int s = 0; s < TOT_STAGES; ++s) {
        load_stage(s + 2);               // prefetch 2 ahead (distinct buffer)
        asm volatile("cp.async.wait_group 2;" ::: "memory");  // stage s landed
        __syncthreads();                 // single barrier per stage

        const int kc = s % KSTEPS;
        if (kc == 0) {
#pragma unroll
            for (int mi = 0; mi < 2; mi++)
#pragma unroll
                for (int nj = 0; nj < 8; nj++)
#pragma unroll
                    for (int c = 0; c < 4; c++) acc[mi][nj][c] = 0;
        }

        const uint32_t As = sb + (s % NSTG) * STAGE_B;
        const uint32_t Bs = As + A_BYTES;

#pragma unroll
        for (int ks = 0; ks < 4; ++ks) {     // 4 x k32 = k128 per stage
            uint32_t a[2][4], b[4][4];
#pragma unroll
            for (int mi = 0; mi < 2; mi++)
                ldm_x4(a[mi], As + aoffL + mi * (16 * 128)
                              + ((((ks * 2 + agr)) ^ aswz) << 4));
#pragma unroll
            for (int j = 0; j < 4; j++)
                ldm_x4(b[j], Bs + boffL + j * (16 * 128)
                             + ((((ks * 2 + bgr)) ^ bswz) << 4));
#pragma unroll
            for (int mi = 0; mi < 2; mi++)
#pragma unroll
                for (int nj = 0; nj < 8; nj++)
                    imma8(acc[mi][nj], a[mi], &b[nj >> 1][(nj & 1) * 2]);
        }

        // ---- per-n-tile epilogue: score = -dot_s32, smem top-2 tracking ---
        if (kc == KSTEPS - 1) {
            const int nb = (s / KSTEPS) * N_TILE + wn * 64 + 2 * (l & 3);
#pragma unroll
            for (int mi = 0; mi < 2; mi++) {
#pragma unroll
                for (int h = 0; h < 2; h++) {
                    const int rs = mi * 2 + h;
#pragma unroll
                    for (int nj = 0; nj < 8; nj++) {
#pragma unroll
                        for (int c = 0; c < 2; c++) {
                            const int n = nb + nj * 8 + c;
                            const float d = -(float)acc[mi][nj][h * 2 + c];
                            if (d < w2[rs]) {        // rare after warmup
                                Cand cd = cands[rs];
                                if (d < cd.d0) {
                                    cd.d1 = cd.d0; cd.i1 = cd.i0;
                                    cd.d0 = d;     cd.i0 = n;
                                } else {
                                    cd.d1 = d;     cd.i1 = n;
                                }
                                cands[rs] = cd;
                                w2[rs] = cd.d1;
                            }
                        }
                    }
                }
            }
        }
    }
    asm volatile("cp.async.wait_group 0;" ::: "memory");

#pragma unroll
    for (int rs = 0; rs < 4; rs++) {
        const int mi = rs >> 1, h = rs & 1;
        const int row = rowBlock + wm * 32 + mi * 16 + h * 8 + (l >> 2);
        const int slot = wn * 4 + (l & 3);
        const int base = row * 32 + slot * 2;
        Cand cd = cands[rs];
        g_cd[base + 0] = cd.d0;  g_ci[base + 0] = cd.i0;
        g_cd[base + 1] = cd.d1;  g_ci[base + 1] = cd.i1;
    }
}

// ---------------------------------------------------------------------------
// Pass 2: exact fp32 refinement (bit-identical to R1 numerics). Warp per row.
// Screen scores in s32-dot units; threshold window 20000 ~ 1e-3 d-units,
// 43 sigma of int8 screen noise.
// ---------------------------------------------------------------------------
__global__ __launch_bounds__(256) void refine_kernel(const float* __restrict__ z,
                                                     const float* __restrict__ emb) {
    const int row  = (blockIdx.x * blockDim.x + threadIdx.x) >> 5;
    const int lane = threadIdx.x & 31;
    const int base = row * 32;

    float da = g_cd[base + lane];
    int   ia = g_ci[base + lane];

    float m = da;
#pragma unroll
    for (int off = 16; off > 0; off >>= 1)
        m = fminf(m, __shfl_xor_sync(0xffffffffu, m, off));
    const float thr = m + MARGIN_S32;

    const float* zp = z + (size_t)row * DDIM;
    const float zf2 = g_zf2[row];

    float fa = FINF;
    if (da <= thr) {
        const float* ep = emb + (size_t)ia * DDIM;
        float acc = 0.0f;
        for (int k = 0; k < DDIM; k++) acc = fmaf(zp[k], ep[k], acc);
        fa = __fadd_rn(__fadd_rn(zf2, g_en2[ia]), -2.0f * acc);
    } else ia = 0x7fffffff;

    float bd = fa; int bi = ia;
#pragma unroll
    for (int off = 16; off > 0; off >>= 1) {
        float od = __shfl_xor_sync(0xffffffffu, bd, off);
        int   oi = __shfl_xor_sync(0xffffffffu, bi, off);
        if (od < bd || (od == bd && oi < bi)) { bd = od; bi = oi; }
    }
    if (lane == 0) g_idx[row] = bi;
}

// ---------------------------------------------------------------------------
// Gather z_q + loss partial (fp32 per-thread, double block tree).
// ---------------------------------------------------------------------------
__global__ void gather_loss_kernel(const float* __restrict__ z,
                                   const float* __restrict__ emb,
                                   float* __restrict__ out) {
    __shared__ double red[256];
    const int bid = blockIdx.x;            // 1024 blocks
    const int base4 = bid * 2048;          // float4 units
    float s = 0.0f;
#pragma unroll 4
    for (int it = 0; it < 8; ++it) {
        const int g = base4 + it * 256 + threadIdx.x;
        const int row = g >> 7;
        const int k4  = g & 127;
        float4 v = *reinterpret_cast<const float4*>(
            emb + (size_t)g_idx[row] * DDIM + k4 * 4);
        *reinterpret_cast<float4*>(out + (size_t)g * 4) = v;
        float4 zz = *reinterpret_cast<const float4*>(z + (size_t)g * 4);
        float dx = v.x - zz.x, dy = v.y - zz.y;
        float dz = v.z - zz.z, dw = v.w - zz.w;
        s = fmaf(dx, dx, s); s = fmaf(dy, dy, s);
        s = fmaf(dz, dz, s); s = fmaf(dw, dw, s);
    }
    red[threadIdx.x] = (double)s;
    __syncthreads();
    for (int off = 128; off > 0; off >>= 1) {
        if (threadIdx.x < off) red[threadIdx.x] += red[threadIdx.x + off];
        __syncthreads();
    }
    if (threadIdx.x == 0) g_partial[bid] = red[0];
}

// ---------------------------------------------------------------------------
// Final scalars. Parallel tree over g_partial.
// ---------------------------------------------------------------------------
__global__ void finalize_kernel(float* __restrict__ out) {
    __shared__ double rs[256], rs2[256], rl[256];
    double s = 0.0, s2 = 0.0;
    for (int i = threadIdx.x; i < BT; i += 256) {
        int iv = g_idx[i];
        out[IDX_OFF + i] = (float)iv;
        double dv = (double)iv;
        s += dv; s2 += dv * dv;
    }
    double lp = 0.0;
#pragma unroll
    for (int j = 0; j < 4; ++j) lp += g_partial[threadIdx.x + j * 256];
    rs[threadIdx.x] = s; rs2[threadIdx.x] = s2; rl[threadIdx.x] = lp;
    __syncthreads();
    for (int off = 128; off > 0; off >>= 1) {
        if (threadIdx.x < off) {
            rs[threadIdx.x]  += rs[threadIdx.x + off];
            rs2[threadIdx.x] += rs2[threadIdx.x + off];
            rl[threadIdx.x]  += rl[threadIdx.x + off];
        }
        __syncthreads();
    }
    if (threadIdx.x == 0) {
        double mse = rl[0] / (double)ZQ_ELEMS;
        out[LOSS_OFF] = (float)((1.0 + BETA) * mse);
        double mean = rs[0] / (double)BT;
        out[VAR_OFF] = (float)(rs2[0] / (double)BT - mean * mean);
    }
}

// ---------------------------------------------------------------------------
extern "C" void kernel_launch(void* const* d_in, const int* in_sizes, int n_in,
                              void* d_out, int out_size) {
    const float* z   = (const float*)d_in[0];
    const float* emb = (const float*)d_in[1];
    float* out = (float*)d_out;

    cudaFuncSetAttribute(vq_mma_kernel,
                         cudaFuncAttributeMaxDynamicSharedMemorySize, SMEM_DYN);

    prep_norms_kernel<<<(NE + BT) / 128, 128>>>(emb, z);       // launch 0
    vq_mma_kernel<<<BT / M_TILE, 512, SMEM_DYN>>>();           // launch 1
    refine_kernel<<<BT * 32 / 256, 256>>>(z, emb);             // launch 2
    gather_loss_kernel<<<1024, 256>>>(z, emb, out);            // launch 3 (ncu)
    finalize_kernel<<<1, 256>>>(out);                          // launch 4
}

// round 16
// speedup vs baseline: 1.8894x; 1.8894x over previous
#include <cuda_runtime.h>
#include <cuda_fp16.h>
#include <cstdint>

// ---------------------------------------------------------------------------
#define BT      16384
#define DDIM    512
#define NE      8192
#define BETA    0.25
#define KTOT    512             // single fp16 plane; exact refine fixes errors

#define ZQ_ELEMS   (BT * DDIM)
#define LOSS_OFF   ZQ_ELEMS
#define IDX_OFF    (ZQ_ELEMS + 1)
#define VAR_OFF    (ZQ_ELEMS + 1 + BT)

#define M_TILE   128
#define N_TILE   256
#define N_TILES  (NE / N_TILE)            // 32
#define KC       64
#define KSTEPS   (KTOT / KC)              // 8
#define TOT_STAGES (N_TILES * KSTEPS)     // 256

#define A_BYTES  (M_TILE * 128)           // 16384
#define B_BYTES  (N_TILE * 128)           // 32768
#define STAGE_B  (A_BYTES + B_BYTES)      // 49152
#define NSTG     4
#define CAND_OFF (NSTG * STAGE_B)         // 196608
#define CAND_B   (512 * 4 * 16)           // 32768
#define SMEM_DYN (CAND_OFF + CAND_B)      // 229376

#define EPS_MARGIN 2e-3f
#define FINF __int_as_float(0x7f800000)

// ---------------------------------------------------------------------------
// Device scratch
// ---------------------------------------------------------------------------
__device__ __align__(256) __half g_zA[BT * KTOT];   // fp16(z)
__device__ __align__(256) __half g_eB[NE * KTOT];   // fp16(emb)
__device__ float  g_zf2[BT];
__device__ float  g_en2[NE];
__device__ int    g_idx[BT];
__device__ double g_partial[1024];
__device__ float  g_cd[BT * 32];   // per-row candidates (16 slots x top-2)
__device__ int    g_ci[BT * 32];

struct Cand { float d0; int i0; float d1; int i1; };

// ---------------------------------------------------------------------------
__device__ __forceinline__ uint32_t smem_u32(const void* p) {
    uint32_t a;
    asm("{ .reg .u64 t; cvta.to.shared.u64 t, %1; cvt.u32.u64 %0, t; }"
        : "=r"(a) : "l"(p));
    return a;
}
__device__ __forceinline__ void cp16(uint32_t dst, const void* src) {
    asm volatile("cp.async.cg.shared.global [%0], [%1], 16;"
                 :: "r"(dst), "l"(src) : "memory");
}
__device__ __forceinline__ void ldm_x4(uint32_t* r, uint32_t addr) {
    asm volatile("ldmatrix.sync.aligned.m8n8.x4.shared.b16 {%0,%1,%2,%3}, [%4];"
                 : "=r"(r[0]), "=r"(r[1]), "=r"(r[2]), "=r"(r[3]) : "r"(addr));
}
// fp16 inputs, fp16 accumulators: D/C are 2 packed-half regs
__device__ __forceinline__ void hmma16(uint32_t* c, const uint32_t* a,
                                       const uint32_t* b) {
    asm volatile(
        "mma.sync.aligned.m16n8k16.row.col.f16.f16.f16.f16 "
        "{%0,%1}, {%2,%3,%4,%5}, {%6,%7}, {%0,%1};"
        : "+r"(c[0]), "+r"(c[1])
        : "r"(a[0]), "r"(a[1]), "r"(a[2]), "r"(a[3]), "r"(b[0]), "r"(b[1]));
}

// ---------------------------------------------------------------------------
// Preprocessing: fp16 plane (vectorized x4, flat layout)
// ---------------------------------------------------------------------------
__global__ void zprep_kernel(const float* __restrict__ z) {
    int i = blockIdx.x * blockDim.x + threadIdx.x;   // float4 index
    float4 v = reinterpret_cast<const float4*>(z)[i];
    __half2 a = __floats2half2_rn(v.x, v.y);
    __half2 b = __floats2half2_rn(v.z, v.w);
    reinterpret_cast<__half2*>(g_zA)[2 * i]     = a;
    reinterpret_cast<__half2*>(g_zA)[2 * i + 1] = b;
}
__global__ void eprep_kernel(const float* __restrict__ emb) {
    int i = blockIdx.x * blockDim.x + threadIdx.x;
    float4 v = reinterpret_cast<const float4*>(emb)[i];
    __half2 a = __floats2half2_rn(v.x, v.y);
    __half2 b = __floats2half2_rn(v.z, v.w);
    reinterpret_cast<__half2*>(g_eB)[2 * i]     = a;
    reinterpret_cast<__half2*>(g_eB)[2 * i + 1] = b;
}

// ---------------------------------------------------------------------------
// Merged row norms. EXACT serial k order per row (refine depends on it).
// Device-symbol writes from device code only (R5/R6 lesson).
// ---------------------------------------------------------------------------
__global__ void norms_kernel(const float* __restrict__ emb,
                             const float* __restrict__ z) {
    __shared__ float buf[128][65];
    const bool is_z = blockIdx.x >= (NE / 128);
    const float* x = is_z ? z : emb;
    const int r0 = (is_z ? (blockIdx.x - NE / 128) : blockIdx.x) * 128;
    float s = 0.0f;
    for (int kc = 0; kc < DDIM; kc += 64) {
        __syncthreads();
#pragma unroll
        for (int i = 0; i < 16; ++i) {
            const int seg = threadIdx.x + i * 128;
            const int r = seg >> 4, c4 = seg & 15;
            float4 v = *reinterpret_cast<const float4*>(
                x + (size_t)(r0 + r) * DDIM + kc + c4 * 4);
            buf[r][c4 * 4 + 0] = v.x; buf[r][c4 * 4 + 1] = v.y;
            buf[r][c4 * 4 + 2] = v.z; buf[r][c4 * 4 + 3] = v.w;
        }
        __syncthreads();
#pragma unroll
        for (int k = 0; k < 64; ++k) {
            float q = __fmul_rn(buf[threadIdx.x][k], buf[threadIdx.x][k]);
            s = __fadd_rn(s, q);
        }
    }
    if (is_z) g_zf2[r0 + threadIdx.x] = s;
    else      g_en2[r0 + threadIdx.x] = s;
}

// ---------------------------------------------------------------------------
// Pass 1 (R12/R13 winner): 4-buffer ring, prefetch 2, single barrier, fp16
// accumulators, smem top-2 candidates. Stage loop unrolled x2 so ptxas can
// interleave consecutive stages' address math and issue windows.
// ---------------------------------------------------------------------------
__global__ __launch_bounds__(512, 1) void vq_mma_kernel() {
    extern __shared__ __align__(1024) char dsm[];

    const int tid = threadIdx.x;
    const int l   = tid & 31;
    const int wid = tid >> 5;
    const int wm  = wid & 3;
    const int wn  = wid >> 2;
    const int rowBlock = blockIdx.x * M_TILE;
    const uint32_t sb = smem_u32(dsm);
    Cand* cands = reinterpret_cast<Cand*>(dsm + CAND_OFF) + tid * 4;

    const int arow = l & 15;
    const int agr  = l >> 4;
    const int brow = (l & 7) | ((l >> 4) << 3);
    const int bgr  = (l >> 3) & 1;
    const uint32_t aoffL = (uint32_t)(wm * 32 + arow) * 128;
    const uint32_t boffL = (uint32_t)(wn * 64 + brow) * 128;
    const int aswz = arow & 7;
    const int bswz = l & 7;

    // hoisted loader geometry (6 segs/thread/stage)
    uint32_t dof[6];
    int      soff[6];
#pragma unroll
    for (int i = 0; i < 6; ++i) {
        const int seg = tid + i * 512;
        if (seg < 1024) {
            const int r = seg >> 3, gs = seg & 7;
            dof[i]  = r * 128 + ((gs ^ (r & 7)) << 4);
            soff[i] = (rowBlock + r) * KTOT + gs * 8;    // into g_zA
        } else {
            const int s2 = seg - 1024;
            const int r = s2 >> 3, gs = s2 & 7;
            dof[i]  = A_BYTES + r * 128 + ((gs ^ (r & 7)) << 4);
            soff[i] = r * KTOT + gs * 8;                 // into g_eB (+ tile off)
        }
    }

    float w2[4];
#pragma unroll
    for (int rs = 0; rs < 4; rs++) {
        w2[rs] = FINF;
        cands[rs].d0 = FINF; cands[rs].i0 = 0x7fffffff;
        cands[rs].d1 = FINF; cands[rs].i1 = 0x7fffffff;
    }

    uint32_t acc[2][8][2];          // fp16 accumulators (packed half2)

    auto load_stage = [&](int s) {
        if (s < TOT_STAGES) {
            const int kcg  = (s % KSTEPS) * KC;
            const int boff = (s / KSTEPS) * (N_TILE * KTOT) + kcg;
            const uint32_t base = sb + (s % NSTG) * STAGE_B;
#pragma unroll
            for (int i = 0; i < 2; ++i)
                cp16(base + dof[i], g_zA + soff[i] + kcg);
#pragma unroll
            for (int i = 2; i < 6; ++i)
                cp16(base + dof[i], g_eB + soff[i] + boff);
        }
        asm volatile("cp.async.commit_group;" ::: "memory");
    };

    load_stage(0);
    load_stage(1);

#pragma unroll 2
    for (int s = 0; s < TOT_STAGES; ++s) {
        load_stage(s + 2);               // prefetch 2 ahead (distinct buffer)
        asm volatile("cp.async.wait_group 2;" ::: "memory");  // stage s landed
        __syncthreads();                 // single barrier per stage

        const int kc = s % KSTEPS;
        if (kc == 0) {
#pragma unroll
            for (int mi = 0; mi < 2; mi++)
#pragma unroll
                for (int nj = 0; nj < 8; nj++) {
                    acc[mi][nj][0] = 0u; acc[mi][nj][1] = 0u;
                }
        }

        const uint32_t As = sb + (s % NSTG) * STAGE_B;
        const uint32_t Bs = As + A_BYTES;

#pragma unroll
        for (int ks = 0; ks < 4; ++ks) {
            uint32_t a[2][4], b[4][4];
#pragma unroll
            for (int mi = 0; mi < 2; mi++)
                ldm_x4(a[mi], As + aoffL + mi * (16 * 128)
                              + ((((ks * 2 + agr)) ^ aswz) << 4));
#pragma unroll
            for (int j = 0; j < 4; j++)
                ldm_x4(b[j], Bs + boffL + j * (16 * 128)
                             + ((((ks * 2 + bgr)) ^ bswz) << 4));
#pragma unroll
            for (int mi = 0; mi < 2; mi++)
#pragma unroll
                for (int nj = 0; nj < 8; nj++)
                    hmma16(acc[mi][nj], a[mi], &b[nj >> 1][(nj & 1) * 2]);
        }

        // ---- per-n-tile epilogue: smem top-2 candidate tracking -----------
        if (kc == KSTEPS - 1) {
            const int nb = (s / KSTEPS) * N_TILE + wn * 64 + 2 * (l & 3);
#pragma unroll
            for (int mi = 0; mi < 2; mi++) {
#pragma unroll
                for (int h = 0; h < 2; h++) {
                    const int rs = mi * 2 + h;
                    const float zf = g_zf2[rowBlock + wm * 32 + mi * 16
                                           + h * 8 + (l >> 2)];
#pragma unroll
                    for (int nj = 0; nj < 8; nj++) {
                        const __half2 h2 =
                            *reinterpret_cast<const __half2*>(&acc[mi][nj][h]);
                        const float2 f2 = __half22float2(h2);
#pragma unroll
                        for (int c = 0; c < 2; c++) {
                            const int n = nb + nj * 8 + c;
                            const float e2 = __ldg(&g_en2[n]);
                            const float dot = (c == 0) ? f2.x : f2.y;
                            const float d = __fadd_rn(__fadd_rn(zf, e2),
                                                      -2.0f * dot);
                            if (d < w2[rs]) {        // rare after warmup
                                Cand cd = cands[rs];
                                if (d < cd.d0) {
                                    cd.d1 = cd.d0; cd.i1 = cd.i0;
                                    cd.d0 = d;     cd.i0 = n;
                                } else {
                                    cd.d1 = d;     cd.i1 = n;
                                }
                                cands[rs] = cd;
                                w2[rs] = cd.d1;
                            }
                        }
                    }
                }
            }
        }
    }
    asm volatile("cp.async.wait_group 0;" ::: "memory");

#pragma unroll
    for (int rs = 0; rs < 4; rs++) {
        const int mi = rs >> 1, h = rs & 1;
        const int row = rowBlock + wm * 32 + mi * 16 + h * 8 + (l >> 2);
        const int slot = wn * 4 + (l & 3);
        const int base = row * 32 + slot * 2;
        Cand cd = cands[rs];
        g_cd[base + 0] = cd.d0;  g_ci[base + 0] = cd.i0;
        g_cd[base + 1] = cd.d1;  g_ci[base + 1] = cd.i1;
    }
}

// ---------------------------------------------------------------------------
// Pass 2: exact fp32 refinement (bit-identical to R1 numerics). Warp per row.
// ---------------------------------------------------------------------------
__global__ __launch_bounds__(256) void refine_kernel(const float* __restrict__ z,
                                                     const float* __restrict__ emb) {
    const int row  = (blockIdx.x * blockDim.x + threadIdx.x) >> 5;
    const int lane = threadIdx.x & 31;
    const int base = row * 32;

    float da = g_cd[base + lane];
    int   ia = g_ci[base + lane];

    float m = da;
#pragma unroll
    for (int off = 16; off > 0; off >>= 1)
        m = fminf(m, __shfl_xor_sync(0xffffffffu, m, off));
    const float thr = m + EPS_MARGIN;

    const float* zp = z + (size_t)row * DDIM;
    const float zf2 = g_zf2[row];

    float fa = FINF;
    if (da <= thr) {
        const float* ep = emb + (size_t)ia * DDIM;
        float acc = 0.0f;
        for (int k = 0; k < DDIM; k++) acc = fmaf(zp[k], ep[k], acc);
        fa = __fadd_rn(__fadd_rn(zf2, g_en2[ia]), -2.0f * acc);
    } else ia = 0x7fffffff;

    float bd = fa; int bi = ia;
#pragma unroll
    for (int off = 16; off > 0; off >>= 1) {
        float od = __shfl_xor_sync(0xffffffffu, bd, off);
        int   oi = __shfl_xor_sync(0xffffffffu, bi, off);
        if (od < bd || (od == bd && oi < bi)) { bd = od; bi = oi; }
    }
    if (lane == 0) g_idx[row] = bi;
}

// ---------------------------------------------------------------------------
// Gather z_q + loss partial (fp32 per-thread, double block tree).
// ---------------------------------------------------------------------------
__global__ void gather_loss_kernel(const float* __restrict__ z,
                                   const float* __restrict__ emb,
                                   float* __restrict__ out) {
    __shared__ double red[256];
    const int bid = blockIdx.x;            // 1024 blocks
    const int base4 = bid * 2048;          // float4 units
    float s = 0.0f;
#pragma unroll 4
    for (int it = 0; it < 8; ++it) {
        const int g = base4 + it * 256 + threadIdx.x;
        const int row = g >> 7;
        const int k4  = g & 127;
        float4 v = *reinterpret_cast<const float4*>(
            emb + (size_t)g_idx[row] * DDIM + k4 * 4);
        *reinterpret_cast<float4*>(out + (size_t)g * 4) = v;
        float4 zz = *reinterpret_cast<const float4*>(z + (size_t)g * 4);
        float dx = v.x - zz.x, dy = v.y - zz.y;
        float dz = v.z - zz.z, dw = v.w - zz.w;
        s = fmaf(dx, dx, s); s = fmaf(dy, dy, s);
        s = fmaf(dz, dz, s); s = fmaf(dw, dw, s);
    }
    red[threadIdx.x] = (double)s;
    __syncthreads();
    for (int off = 128; off > 0; off >>= 1) {
        if (threadIdx.x < off) red[threadIdx.x] += red[threadIdx.x + off];
        __syncthreads();
    }
    if (threadIdx.x == 0) g_partial[bid] = red[0];
}

// ---------------------------------------------------------------------------
// Final scalars. Parallel tree over g_partial.
// ---------------------------------------------------------------------------
__global__ void finalize_kernel(float* __restrict__ out) {
    __shared__ double rs[256], rs2[256], rl[256];
    double s = 0.0, s2 = 0.0;
    for (int i = threadIdx.x; i < BT; i += 256) {
        int iv = g_idx[i];
        out[IDX_OFF + i] = (float)iv;
        double dv = (double)iv;
        s += dv; s2 += dv * dv;
    }
    double lp = 0.0;
#pragma unroll
    for (int j = 0; j < 4; ++j) lp += g_partial[threadIdx.x + j * 256];
    rs[threadIdx.x] = s; rs2[threadIdx.x] = s2; rl[threadIdx.x] = lp;
    __syncthreads();
    for (int off = 128; off > 0; off >>= 1) {
        if (threadIdx.x < off) {
            rs[threadIdx.x]  += rs[threadIdx.x + off];
            rs2[threadIdx.x] += rs2[threadIdx.x + off];
            rl[threadIdx.x]  += rl[threadIdx.x + off];
        }
        __syncthreads();
    }
    if (threadIdx.x == 0) {
        double mse = rl[0] / (double)ZQ_ELEMS;
        out[LOSS_OFF] = (float)((1.0 + BETA) * mse);
        double mean = rs[0] / (double)BT;
        out[VAR_OFF] = (float)(rs2[0] / (double)BT - mean * mean);
    }
}

// ---------------------------------------------------------------------------
extern "C" void kernel_launch(void* const* d_in, const int* in_sizes, int n_in,
                              void* d_out, int out_size) {
    const float* z   = (const float*)d_in[0];
    const float* emb = (const float*)d_in[1];
    float* out = (float*)d_out;

    cudaFuncSetAttribute(vq_mma_kernel,
                         cudaFuncAttributeMaxDynamicSharedMemorySize, SMEM_DYN);

    zprep_kernel<<<ZQ_ELEMS / 4 / 256, 256>>>(z);              // launch 0
    eprep_kernel<<<NE * DDIM / 4 / 256, 256>>>(emb);           // launch 1
    norms_kernel<<<(NE + BT) / 128, 128>>>(emb, z);            // launch 2
    vq_mma_kernel<<<BT / M_TILE, 512, SMEM_DYN>>>();           // launch 3 (ncu)
    refine_kernel<<<BT * 32 / 256, 256>>>(z, emb);
    gather_loss_kernel<<<1024, 256>>>(z, emb, out);
    finalize_kernel<<<1, 256>>>(out);
}

// round 17
// speedup vs baseline: 2.0014x; 1.0593x over previous
#include <cuda_runtime.h>
#include <cuda_fp16.h>
#include <cstdint>

// ---------------------------------------------------------------------------
#define BT      16384
#define DDIM    512
#define NE      8192
#define BETA    0.25
#define KTOT    512             // single fp16 plane; exact refine fixes errors

#define ZQ_ELEMS   (BT * DDIM)
#define LOSS_OFF   ZQ_ELEMS
#define IDX_OFF    (ZQ_ELEMS + 1)
#define VAR_OFF    (ZQ_ELEMS + 1 + BT)

#define M_TILE   128
#define N_TILE   256
#define N_TILES  (NE / N_TILE)            // 32
#define KC       64
#define KSTEPS   (KTOT / KC)              // 8
#define TOT_STAGES (N_TILES * KSTEPS)     // 256

#define A_BYTES  (M_TILE * 128)           // 16384
#define B_BYTES  (N_TILE * 128)           // 32768
#define STAGE_B  (A_BYTES + B_BYTES)      // 49152
#define NSTG     4
#define CAND_OFF (NSTG * STAGE_B)         // 196608
#define CAND_B   (512 * 4 * 16)           // 32768
#define SMEM_DYN (CAND_OFF + CAND_B)      // 229376

#define EPS_MARGIN 2e-3f
#define FINF __int_as_float(0x7f800000)

// ---------------------------------------------------------------------------
// Device scratch
// ---------------------------------------------------------------------------
__device__ __align__(256) __half g_zA[BT * KTOT];   // fp16(z)
__device__ __align__(256) __half g_eB[NE * KTOT];   // fp16(emb)
__device__ float  g_zf2[BT];
__device__ float  g_en2[NE];
__device__ int    g_idx[BT];
__device__ double g_partial[1024];
__device__ float  g_cd[BT * 32];   // per-row candidates (16 slots x top-2)
__device__ int    g_ci[BT * 32];

struct Cand { float d0; int i0; float d1; int i1; };

// ---------------------------------------------------------------------------
__device__ __forceinline__ uint32_t smem_u32(const void* p) {
    uint32_t a;
    asm("{ .reg .u64 t; cvta.to.shared.u64 t, %1; cvt.u32.u64 %0, t; }"
        : "=r"(a) : "l"(p));
    return a;
}
__device__ __forceinline__ void cp16(uint32_t dst, const void* src) {
    asm volatile("cp.async.cg.shared.global [%0], [%1], 16;"
                 :: "r"(dst), "l"(src) : "memory");
}
__device__ __forceinline__ void ldm_x4(uint32_t* r, uint32_t addr) {
    asm volatile("ldmatrix.sync.aligned.m8n8.x4.shared.b16 {%0,%1,%2,%3}, [%4];"
                 : "=r"(r[0]), "=r"(r[1]), "=r"(r[2]), "=r"(r[3]) : "r"(addr));
}
// fp16 inputs, fp16 accumulators: D/C are 2 packed-half regs
__device__ __forceinline__ void hmma16(uint32_t* c, const uint32_t* a,
                                       const uint32_t* b) {
    asm volatile(
        "mma.sync.aligned.m16n8k16.row.col.f16.f16.f16.f16 "
        "{%0,%1}, {%2,%3,%4,%5}, {%6,%7}, {%0,%1};"
        : "+r"(c[0]), "+r"(c[1])
        : "r"(a[0]), "r"(a[1]), "r"(a[2]), "r"(a[3]), "r"(b[0]), "r"(b[1]));
}

// ---------------------------------------------------------------------------
// Preprocessing: fp16 plane (vectorized x4, flat layout)
// ---------------------------------------------------------------------------
__global__ void zprep_kernel(const float* __restrict__ z) {
    int i = blockIdx.x * blockDim.x + threadIdx.x;   // float4 index
    float4 v = reinterpret_cast<const float4*>(z)[i];
    __half2 a = __floats2half2_rn(v.x, v.y);
    __half2 b = __floats2half2_rn(v.z, v.w);
    reinterpret_cast<__half2*>(g_zA)[2 * i]     = a;
    reinterpret_cast<__half2*>(g_zA)[2 * i + 1] = b;
}
__global__ void eprep_kernel(const float* __restrict__ emb) {
    int i = blockIdx.x * blockDim.x + threadIdx.x;
    float4 v = reinterpret_cast<const float4*>(emb)[i];
    __half2 a = __floats2half2_rn(v.x, v.y);
    __half2 b = __floats2half2_rn(v.z, v.w);
    reinterpret_cast<__half2*>(g_eB)[2 * i]     = a;
    reinterpret_cast<__half2*>(g_eB)[2 * i + 1] = b;
}

// ---------------------------------------------------------------------------
// Merged row norms. EXACT serial k order per row (refine depends on it).
// Device-symbol writes from device code only (R5/R6 lesson).
// ---------------------------------------------------------------------------
__global__ void norms_kernel(const float* __restrict__ emb,
                             const float* __restrict__ z) {
    __shared__ float buf[128][65];
    const bool is_z = blockIdx.x >= (NE / 128);
    const float* x = is_z ? z : emb;
    const int r0 = (is_z ? (blockIdx.x - NE / 128) : blockIdx.x) * 128;
    float s = 0.0f;
    for (int kc = 0; kc < DDIM; kc += 64) {
        __syncthreads();
#pragma unroll
        for (int i = 0; i < 16; ++i) {
            const int seg = threadIdx.x + i * 128;
            const int r = seg >> 4, c4 = seg & 15;
            float4 v = *reinterpret_cast<const float4*>(
                x + (size_t)(r0 + r) * DDIM + kc + c4 * 4);
            buf[r][c4 * 4 + 0] = v.x; buf[r][c4 * 4 + 1] = v.y;
            buf[r][c4 * 4 + 2] = v.z; buf[r][c4 * 4 + 3] = v.w;
        }
        __syncthreads();
#pragma unroll
        for (int k = 0; k < 64; ++k) {
            float q = __fmul_rn(buf[threadIdx.x][k], buf[threadIdx.x][k]);
            s = __fadd_rn(s, q);
        }
    }
    if (is_z) g_zf2[r0 + threadIdx.x] = s;
    else      g_en2[r0 + threadIdx.x] = s;
}

// ---------------------------------------------------------------------------
// Pass 1: 4-buffer ring, prefetch 2, single barrier, fp16 accumulators, smem
// top-2 candidates. Outer loop over n-tiles with the 8 k-stages UNROLLED so
// kc is compile-time: reset only in body 0, epilogue only in body 7, no
// modular math in the hot path.
// ---------------------------------------------------------------------------
__global__ __launch_bounds__(512, 1) void vq_mma_kernel() {
    extern __shared__ __align__(1024) char dsm[];

    const int tid = threadIdx.x;
    const int l   = tid & 31;
    const int wid = tid >> 5;
    const int wm  = wid & 3;
    const int wn  = wid >> 2;
    const int rowBlock = blockIdx.x * M_TILE;
    const uint32_t sb = smem_u32(dsm);
    Cand* cands = reinterpret_cast<Cand*>(dsm + CAND_OFF) + tid * 4;

    const int arow = l & 15;
    const int agr  = l >> 4;
    const int brow = (l & 7) | ((l >> 4) << 3);
    const int bgr  = (l >> 3) & 1;
    const uint32_t aoffL = (uint32_t)(wm * 32 + arow) * 128;
    const uint32_t boffL = (uint32_t)(wn * 64 + brow) * 128;
    const int aswz = arow & 7;
    const int bswz = l & 7;

    // hoisted loader geometry (6 segs/thread/stage)
    uint32_t dof[6];
    int      soff[6];
#pragma unroll
    for (int i = 0; i < 6; ++i) {
        const int seg = tid + i * 512;
        if (seg < 1024) {
            const int r = seg >> 3, gs = seg & 7;
            dof[i]  = r * 128 + ((gs ^ (r & 7)) << 4);
            soff[i] = (rowBlock + r) * KTOT + gs * 8;    // into g_zA
        } else {
            const int s2 = seg - 1024;
            const int r = s2 >> 3, gs = s2 & 7;
            dof[i]  = A_BYTES + r * 128 + ((gs ^ (r & 7)) << 4);
            soff[i] = r * KTOT + gs * 8;                 // into g_eB (+ tile off)
        }
    }

    float w2[4];
#pragma unroll
    for (int rs = 0; rs < 4; rs++) {
        w2[rs] = FINF;
        cands[rs].d0 = FINF; cands[rs].i0 = 0x7fffffff;
        cands[rs].d1 = FINF; cands[rs].i1 = 0x7fffffff;
    }

    uint32_t acc[2][8][2];          // fp16 accumulators (packed half2)

    auto load_stage = [&](int s) {
        if (s < TOT_STAGES) {
            const int kcg  = (s & (KSTEPS - 1)) * KC;
            const int boff = (s >> 3) * (N_TILE * KTOT) + kcg;
            const uint32_t base = sb + (s & (NSTG - 1)) * STAGE_B;
#pragma unroll
            for (int i = 0; i < 2; ++i)
                cp16(base + dof[i], g_zA + soff[i] + kcg);
#pragma unroll
            for (int i = 2; i < 6; ++i)
                cp16(base + dof[i], g_eB + soff[i] + boff);
        }
        asm volatile("cp.async.commit_group;" ::: "memory");
    };

    load_stage(0);
    load_stage(1);

    for (int t = 0; t < N_TILES; ++t) {
#pragma unroll
        for (int kc = 0; kc < KSTEPS; ++kc) {
            const int s = t * KSTEPS + kc;
            load_stage(s + 2);           // prefetch 2 ahead (distinct buffer)
            asm volatile("cp.async.wait_group 2;" ::: "memory");
            __syncthreads();             // single barrier per stage

            if (kc == 0) {
#pragma unroll
                for (int mi = 0; mi < 2; mi++)
#pragma unroll
                    for (int nj = 0; nj < 8; nj++) {
                        acc[mi][nj][0] = 0u; acc[mi][nj][1] = 0u;
                    }
            }

            const uint32_t As = sb + (s & (NSTG - 1)) * STAGE_B;
            const uint32_t Bs = As + A_BYTES;

#pragma unroll
            for (int ks = 0; ks < 4; ++ks) {
                uint32_t a[2][4], b[4][4];
#pragma unroll
                for (int mi = 0; mi < 2; mi++)
                    ldm_x4(a[mi], As + aoffL + mi * (16 * 128)
                                  + ((((ks * 2 + agr)) ^ aswz) << 4));
#pragma unroll
                for (int j = 0; j < 4; j++)
                    ldm_x4(b[j], Bs + boffL + j * (16 * 128)
                                 + ((((ks * 2 + bgr)) ^ bswz) << 4));
#pragma unroll
                for (int mi = 0; mi < 2; mi++)
#pragma unroll
                    for (int nj = 0; nj < 8; nj++)
                        hmma16(acc[mi][nj], a[mi], &b[nj >> 1][(nj & 1) * 2]);
            }

            // ---- epilogue only in the last unrolled body ------------------
            if (kc == KSTEPS - 1) {
                const int nb = t * N_TILE + wn * 64 + 2 * (l & 3);
#pragma unroll
                for (int mi = 0; mi < 2; mi++) {
#pragma unroll
                    for (int h = 0; h < 2; h++) {
                        const int rs = mi * 2 + h;
                        const float zf = g_zf2[rowBlock + wm * 32 + mi * 16
                                               + h * 8 + (l >> 2)];
#pragma unroll
                        for (int nj = 0; nj < 8; nj++) {
                            const __half2 h2 =
                                *reinterpret_cast<const __half2*>(&acc[mi][nj][h]);
                            const float2 f2 = __half22float2(h2);
#pragma unroll
                            for (int c = 0; c < 2; c++) {
                                const int n = nb + nj * 8 + c;
                                const float e2 = __ldg(&g_en2[n]);
                                const float dot = (c == 0) ? f2.x : f2.y;
                                const float d = __fadd_rn(__fadd_rn(zf, e2),
                                                          -2.0f * dot);
                                if (d < w2[rs]) {    // rare after warmup
                                    Cand cd = cands[rs];
                                    if (d < cd.d0) {
                                        cd.d1 = cd.d0; cd.i1 = cd.i0;
                                        cd.d0 = d;     cd.i0 = n;
                                    } else {
                                        cd.d1 = d;     cd.i1 = n;
                                    }
                                    cands[rs] = cd;
                                    w2[rs] = cd.d1;
                                }
                            }
                        }
                    }
                }
            }
        }
    }
    asm volatile("cp.async.wait_group 0;" ::: "memory");

#pragma unroll
    for (int rs = 0; rs < 4; rs++) {
        const int mi = rs >> 1, h = rs & 1;
        const int row = rowBlock + wm * 32 + mi * 16 + h * 8 + (l >> 2);
        const int slot = wn * 4 + (l & 3);
        const int base = row * 32 + slot * 2;
        Cand cd = cands[rs];
        g_cd[base + 0] = cd.d0;  g_ci[base + 0] = cd.i0;
        g_cd[base + 1] = cd.d1;  g_ci[base + 1] = cd.i1;
    }
}

// ---------------------------------------------------------------------------
// Pass 2: exact fp32 refinement (bit-identical to R1 numerics). Warp per row.
// ---------------------------------------------------------------------------
__global__ __launch_bounds__(256) void refine_kernel(const float* __restrict__ z,
                                                     const float* __restrict__ emb) {
    const int row  = (blockIdx.x * blockDim.x + threadIdx.x) >> 5;
    const int lane = threadIdx.x & 31;
    const int base = row * 32;

    float da = g_cd[base + lane];
    int   ia = g_ci[base + lane];

    float m = da;
#pragma unroll
    for (int off = 16; off > 0; off >>= 1)
        m = fminf(m, __shfl_xor_sync(0xffffffffu, m, off));
    const float thr = m + EPS_MARGIN;

    const float* zp = z + (size_t)row * DDIM;
    const float zf2 = g_zf2[row];

    float fa = FINF;
    if (da <= thr) {
        const float* ep = emb + (size_t)ia * DDIM;
        float acc = 0.0f;
        for (int k = 0; k < DDIM; k++) acc = fmaf(zp[k], ep[k], acc);
        fa = __fadd_rn(__fadd_rn(zf2, g_en2[ia]), -2.0f * acc);
    } else ia = 0x7fffffff;

    float bd = fa; int bi = ia;
#pragma unroll
    for (int off = 16; off > 0; off >>= 1) {
        float od = __shfl_xor_sync(0xffffffffu, bd, off);
        int   oi = __shfl_xor_sync(0xffffffffu, bi, off);
        if (od < bd || (od == bd && oi < bi)) { bd = od; bi = oi; }
    }
    if (lane == 0) g_idx[row] = bi;
}

// ---------------------------------------------------------------------------
// Gather z_q + loss partial (fp32 per-thread, double block tree).
// ---------------------------------------------------------------------------
__global__ void gather_loss_kernel(const float* __restrict__ z,
                                   const float* __restrict__ emb,
                                   float* __restrict__ out) {
    __shared__ double red[256];
    const int bid = blockIdx.x;            // 1024 blocks
    const int base4 = bid * 2048;          // float4 units
    float s = 0.0f;
#pragma unroll 4
    for (int it = 0; it < 8; ++it) {
        const int g = base4 + it * 256 + threadIdx.x;
        const int row = g >> 7;
        const int k4  = g & 127;
        float4 v = *reinterpret_cast<const float4*>(
            emb + (size_t)g_idx[row] * DDIM + k4 * 4);
        *reinterpret_cast<float4*>(out + (size_t)g * 4) = v;
        float4 zz = *reinterpret_cast<const float4*>(z + (size_t)g * 4);
        float dx = v.x - zz.x, dy = v.y - zz.y;
        float dz = v.z - zz.z, dw = v.w - zz.w;
        s = fmaf(dx, dx, s); s = fmaf(dy, dy, s);
        s = fmaf(dz, dz, s); s = fmaf(dw, dw, s);
    }
    red[threadIdx.x] = (double)s;
    __syncthreads();
    for (int off = 128; off > 0; off >>= 1) {
        if (threadIdx.x < off) red[threadIdx.x] += red[threadIdx.x + off];
        __syncthreads();
    }
    if (threadIdx.x == 0) g_partial[bid] = red[0];
}

// ---------------------------------------------------------------------------
// Final scalars. Parallel tree over g_partial.
// ---------------------------------------------------------------------------
__global__ void finalize_kernel(float* __restrict__ out) {
    __shared__ double rs[256], rs2[256], rl[256];
    double s = 0.0, s2 = 0.0;
    for (int i = threadIdx.x; i < BT; i += 256) {
        int iv = g_idx[i];
        out[IDX_OFF + i] = (float)iv;
        double dv = (double)iv;
        s += dv; s2 += dv * dv;
    }
    double lp = 0.0;
#pragma unroll
    for (int j = 0; j < 4; ++j) lp += g_partial[threadIdx.x + j * 256];
    rs[threadIdx.x] = s; rs2[threadIdx.x] = s2; rl[threadIdx.x] = lp;
    __syncthreads();
    for (int off = 128; off > 0; off >>= 1) {
        if (threadIdx.x < off) {
            rs[threadIdx.x]  += rs[threadIdx.x + off];
            rs2[threadIdx.x] += rs2[threadIdx.x + off];
            rl[threadIdx.x]  += rl[threadIdx.x + off];
        }
        __syncthreads();
    }
    if (threadIdx.x == 0) {
        double mse = rl[0] / (double)ZQ_ELEMS;
        out[LOSS_OFF] = (float)((1.0 + BETA) * mse);
        double mean = rs[0] / (double)BT;
        out[VAR_OFF] = (float)(rs2[0] / (double)BT - mean * mean);
    }
}

// ---------------------------------------------------------------------------
extern "C" void kernel_launch(void* const* d_in, const int* in_sizes, int n_in,
                              void* d_out, int out_size) {
    const float* z   = (const float*)d_in[0];
    const float* emb = (const float*)d_in[1];
    float* out = (float*)d_out;

    cudaFuncSetAttribute(vq_mma_kernel,
                         cudaFuncAttributeMaxDynamicSharedMemorySize, SMEM_DYN);

    zprep_kernel<<<ZQ_ELEMS / 4 / 256, 256>>>(z);              // launch 0
    eprep_kernel<<<NE * DDIM / 4 / 256, 256>>>(emb);           // launch 1
    norms_kernel<<<(NE + BT) / 128, 128>>>(emb, z);            // launch 2
    vq_mma_kernel<<<BT / M_TILE, 512, SMEM_DYN>>>();           // launch 3 (ncu)
    refine_kernel<<<BT * 32 / 256, 256>>>(z, emb);
    gather_loss_kernel<<<1024, 256>>>(z, emb, out);
    finalize_kernel<<<1, 256>>>(out);
}